// round 17
// baseline (speedup 1.0000x reference)
#include <cuda_runtime.h>
#include <cuda_bf16.h>
#include <cstdint>

// ===================== problem constants =====================
constexpr int Nn = 8192;
constexpr int Dd = 768;
constexpr int BM = 128;            // Q rows per job
constexpr int BN = 128;            // C cols per tile
constexpr int BK = 64;             // K per SMEM chunk (64 bf16 = 128B rows)
constexpr int NKC = Dd / BK;       // 12 K-chunks
constexpr int COLSPLIT = 16;       // by range
constexpr int CHUNKS = (Nn / BN) / COLSPLIT;  // 4 col tiles per job
constexpr int TOT = CHUNKS * NKC;  // 48 B-chunk iterations per job
constexpr int NJOBS = (Nn / BM) * COLSPLIT;   // 1024
constexpr int NUNITS = Nn / 128;   // 64 readiness units (128 rows of q AND c)
// q rows pre-scaled by 20*log2(e): accumulators are base-2 logits directly
constexpr float QSCALE = 20.0f * 1.4426950408889634f;
constexpr float D2SC = 28.853900817779268f;   // 20*log2(e)
constexpr float LN2 = 0.6931471805599453f;

constexpr int A_BYTES = BM * Dd * 2;                    // 196608
constexpr int B_OFF   = A_BYTES;
constexpr int SMEM_BYTES = A_BYTES + 2 * BN * BK * 2;   // 229376

// ===================== device scratch =====================
__device__ __align__(16) __nv_bfloat16 g_qn[(size_t)Nn * Dd];
__device__ __align__(16) __nv_bfloat16 g_cn[(size_t)Nn * Dd];
__device__ float g_rows[COLSPLIT][Nn];
__device__ float g_diag[Nn];   // exact fp32 diagonal, base-2 scaled
__device__ int   g_cnt[NUNITS];  // rows completed per unit
__device__ int   g_total;        // total rows completed

// ===================== helpers =====================
__device__ __forceinline__ uint32_t smem_u32(const void* p) {
    uint32_t a;
    asm("{ .reg .u64 t; cvta.to.shared.u64 t, %1; cvt.u32.u64 %0, t; }"
        : "=r"(a) : "l"(p));
    return a;
}

#define SMEM_SWIZZLE_128B(o) ((o) ^ (((o) >> 3) & 0x70))

__device__ __forceinline__ void cp16(uint32_t dst, const void* src) {
    asm volatile("cp.async.cg.shared.global [%0], [%1], 16;" :: "r"(dst), "l"(src));
}
#define CP_COMMIT asm volatile("cp.async.commit_group;" ::: "memory")
#define CP_WAIT0  asm volatile("cp.async.wait_group 0;" ::: "memory")

__device__ __forceinline__ void ldm4(uint32_t* r, uint32_t addr) {
    asm volatile("ldmatrix.sync.aligned.m8n8.x4.shared.b16 {%0,%1,%2,%3}, [%4];"
        : "=r"(r[0]), "=r"(r[1]), "=r"(r[2]), "=r"(r[3]) : "r"(addr));
}

__device__ __forceinline__ void mma16816(float* d, const uint32_t* a,
                                         uint32_t b0, uint32_t b1) {
    asm volatile(
        "mma.sync.aligned.m16n8k16.row.col.f32.bf16.bf16.f32 "
        "{%0,%1,%2,%3}, {%4,%5,%6,%7}, {%8,%9}, {%0,%1,%2,%3};"
        : "+f"(d[0]), "+f"(d[1]), "+f"(d[2]), "+f"(d[3])
        : "r"(a[0]), "r"(a[1]), "r"(a[2]), "r"(a[3]), "r"(b0), "r"(b1));
}

__device__ __forceinline__ float ex2f(float x) {
    float y;
    asm("ex2.approx.f32 %0, %1;" : "=f"(y) : "f"(x));
    return y;
}

// L2 (L1-bypassing) load — for readiness counters
__device__ __forceinline__ int ldcg(const int* p) {
    int v;
    asm volatile("ld.global.cg.b32 %0, [%1];" : "=r"(v) : "l"(p));
    return v;
}

// ===================== kernel 0: reset readiness counters =====================
__global__ void init_kernel() {
    if (threadIdx.x < NUNITS) g_cnt[threadIdx.x] = 0;
    if (threadIdx.x == NUNITS) g_total = 0;
}

// ===================== kernel 1: fused norm + persistent GEMM =====================
// Phase A: warps normalize rows STRIDED across the whole grid so 128-row
// units complete in a staircase; each row bumps its unit counter.
// Phase B: persistent GEMM (R14 structure); each job first waits (L2 spin)
// for its q-unit and 4 c-units, enabling norm/GEMM overlap.
__global__ void __launch_bounds__(256, 1) simcse_fused(const float* __restrict__ q,
                                                       const float* __restrict__ c) {
    extern __shared__ __align__(1024) uint8_t smem[];
    uint8_t* sA = smem;           // 12 chunks of [128 rows][128B] SW128 K-major
    uint8_t* sB = smem + B_OFF;   // 2 buffers of [128 rows][128B] SW128 K-major

    const int tid = threadIdx.x;
    const int lane = tid & 31;
    const int wid = tid >> 5;
    const int ncta = gridDim.x;

    // ================= Phase A: normalization (strided warp-per-row) =========
    {
        const int W = ncta * 8;
        const int wg = blockIdx.x * 8 + wid;
#pragma unroll 1
        for (int row = wg; row < Nn; row += W) {
            const float4* qs = reinterpret_cast<const float4*>(q + (size_t)row * Dd);
            const float4* cs = reinterpret_cast<const float4*>(c + (size_t)row * Dd);

            float4 qv[6], cv[6];
            float qq = 0.f, cc = 0.f, qcv = 0.f;
#pragma unroll
            for (int j = 0; j < 6; j++) {
                qv[j] = qs[lane + j * 32];
                cv[j] = cs[lane + j * 32];
                qq += qv[j].x * qv[j].x + qv[j].y * qv[j].y +
                      qv[j].z * qv[j].z + qv[j].w * qv[j].w;
                cc += cv[j].x * cv[j].x + cv[j].y * cv[j].y +
                      cv[j].z * cv[j].z + cv[j].w * cv[j].w;
                qcv += qv[j].x * cv[j].x + qv[j].y * cv[j].y +
                       qv[j].z * cv[j].z + qv[j].w * cv[j].w;
            }
#pragma unroll
            for (int o = 16; o; o >>= 1) {
                qq += __shfl_xor_sync(0xFFFFFFFFu, qq, o);
                cc += __shfl_xor_sync(0xFFFFFFFFu, cc, o);
                qcv += __shfl_xor_sync(0xFFFFFFFFu, qcv, o);
            }
            const float nq = fmaxf(sqrtf(qq), 1e-8f);
            const float nc = fmaxf(sqrtf(cc), 1e-8f);
            if (lane == 0) g_diag[row] = D2SC * qcv / (nq * nc);

            const float sq = QSCALE / nq, sc = 1.0f / nc;
            uint2* qd = reinterpret_cast<uint2*>(g_qn + (size_t)row * Dd);
            uint2* cd = reinterpret_cast<uint2*>(g_cn + (size_t)row * Dd);
#pragma unroll
            for (int j = 0; j < 6; j++) {
                __nv_bfloat162 q0 = __float22bfloat162_rn(
                    make_float2(qv[j].x * sq, qv[j].y * sq));
                __nv_bfloat162 q1 = __float22bfloat162_rn(
                    make_float2(qv[j].z * sq, qv[j].w * sq));
                __nv_bfloat162 c0 = __float22bfloat162_rn(
                    make_float2(cv[j].x * sc, cv[j].y * sc));
                __nv_bfloat162 c1 = __float22bfloat162_rn(
                    make_float2(cv[j].z * sc, cv[j].w * sc));
                qd[lane + j * 32] = make_uint2(*(uint32_t*)&q0, *(uint32_t*)&q1);
                cd[lane + j * 32] = make_uint2(*(uint32_t*)&c0, *(uint32_t*)&c1);
            }
            if (lane == 0) {
                __threadfence();   // data visible at L2 before counter bump
                atomicAdd(&g_cnt[row >> 7], 1);
                atomicAdd(&g_total, 1);
            }
        }
    }

    // ================= Phase B: persistent GEMM (R14-validated) ==============
    const int warp_m = wid >> 1;   // 0..3 (32 rows each)
    const int warp_n = wid & 1;    // 0..1 (64 cols each)

    const uint32_t sA_u = smem_u32(sA);
    const uint32_t sB_u = smem_u32(sB);

    const uint32_t aoff0 = (uint32_t)((lane & 15) * 128 + (lane >> 4) * 16) +
                           (uint32_t)warp_m * 4096u;
    const uint32_t boff0 = (uint32_t)(((((lane >> 4) & 1) * 8) + (lane & 7)) * 128 +
                                      ((lane >> 3) & 1) * 16) +
                           (uint32_t)warp_n * 8192u;

    const int lo = (int)(((long long)blockIdx.x * NJOBS) / ncta);
    const int hi = (int)(((long long)(blockIdx.x + 1) * NJOBS) / ncta);
    int prev_bx = -1;
    bool flags_done = false;   // meaningful on tid0 only

    float acc[2][8][4];
    float eacc[2][8][4];
#pragma unroll
    for (int mt = 0; mt < 2; mt++)
#pragma unroll
        for (int nt = 0; nt < 8; nt++)
#pragma unroll
            for (int d = 0; d < 4; d++) acc[mt][nt][d] = 0.f;

#pragma unroll 1
    for (int job = lo; job < hi; job++) {
        const int bx = job >> 4;       // row block 0..63
        const int by = job & 15;       // col split 0..15

        // ---- readiness wait: q-unit bx + c-units 4*by..4*by+3 ----
        if (tid == 0 && !flags_done) {
            if (ldcg(&g_total) >= Nn) {
                flags_done = true;
            } else {
                const int u0 = by * 4;
                for (;;) {
                    int m0 = ldcg(&g_cnt[u0 + 0]);
                    int m1 = ldcg(&g_cnt[u0 + 1]);
                    int m2 = ldcg(&g_cnt[u0 + 2]);
                    int m3 = ldcg(&g_cnt[u0 + 3]);
                    int mq = ldcg(&g_cnt[bx]);
                    int mn = min(min(min(m0, m1), min(m2, m3)), mq);
                    if (mn >= 128) break;
                    __nanosleep(256);
                }
            }
        }
        __syncthreads();

        // ---- stage A on bx change: 128 Q rows (192KB) via cp.async ----
        if (bx != prev_bx) {
            const __nv_bfloat16* qbase = g_qn + (size_t)bx * BM * Dd;
#pragma unroll 4
            for (int i = 0; i < 48; i++) {
                int idx = tid + i * 256;        // 0..12287 (16B units)
                int kc = idx >> 10;
                int pos = idx & 1023;
                int r = pos >> 3, cg = pos & 7;
                const void* src = qbase + (size_t)r * Dd + kc * BK + cg * 8;
                uint32_t dst = sA_u + kc * 16384 +
                               SMEM_SWIZZLE_128B((uint32_t)(r * 128 + cg * 16));
                cp16(dst, src);
            }
            prev_bx = bx;
        }

        const __nv_bfloat16* cquad = g_cn + (size_t)by * CHUNKS * BN * Dd;

        auto loadB = [&](int g, int buf) {
            const int t = g / NKC, kc = g % NKC;
            const __nv_bfloat16* cb = cquad + (size_t)t * BN * Dd + kc * BK;
#pragma unroll
            for (int i = 0; i < 4; i++) {
                int pos = tid + i * 256;        // 0..1023
                int r = pos >> 3, cg = pos & 7;
                cp16(sB_u + buf * 16384 +
                         SMEM_SWIZZLE_128B((uint32_t)(r * 128 + cg * 16)),
                     cb + (size_t)r * Dd + cg * 8);
            }
            CP_COMMIT;
        };

        loadB(0, 0);  // (A's cp.asyncs, if any, join this commit group)

        float rsum[2][2] = {{0.f, 0.f}, {0.f, 0.f}};
        bool pending = false;

        auto chunk = [&](int g, int kc) {
            const int buf = g & 1;
            CP_WAIT0;            // this chunk's B tile (and A if staged) resident
            __syncthreads();     // publish buf to all threads; protect buf^1
            if (g + 1 < TOT) loadB(g + 1, buf ^ 1);

            const uint32_t abase = sA_u + (uint32_t)kc * 16384u;
            const uint32_t bbase = sB_u + (uint32_t)buf * 16384u;

            uint32_t a[2][2][4], b[2][4][4];
#pragma unroll
            for (int mt = 0; mt < 2; mt++)
                ldm4(a[0][mt], abase + SMEM_SWIZZLE_128B(aoff0 + (uint32_t)(mt * 2048)));
#pragma unroll
            for (int ntp = 0; ntp < 4; ntp++)
                ldm4(b[0][ntp], bbase + SMEM_SWIZZLE_128B(boff0 + (uint32_t)(ntp * 2048)));

#pragma unroll
            for (int kk = 0; kk < 4; kk++) {
                const int cur = kk & 1, nxt = cur ^ 1;
                if (kk < 3) {
#pragma unroll
                    for (int mt = 0; mt < 2; mt++)
                        ldm4(a[nxt][mt], abase + SMEM_SWIZZLE_128B(
                                 aoff0 + (uint32_t)(mt * 2048 + (kk + 1) * 32)));
#pragma unroll
                    for (int ntp = 0; ntp < 4; ntp++)
                        ldm4(b[nxt][ntp], bbase + SMEM_SWIZZLE_128B(
                                 boff0 + (uint32_t)(ntp * 2048 + (kk + 1) * 32)));
                }
#pragma unroll
                for (int mt = 0; mt < 2; mt++)
#pragma unroll
                    for (int ntp = 0; ntp < 4; ntp++) {
                        mma16816(acc[mt][2 * ntp + 0], a[cur][mt],
                                 b[cur][ntp][0], b[cur][ntp][1]);
                        mma16816(acc[mt][2 * ntp + 1], a[cur][mt],
                                 b[cur][ntp][2], b[cur][ntp][3]);
                    }
            }
        };

#pragma unroll 1
        for (int t = 0; t < CHUNKS; t++) {
#pragma unroll
            for (int kcp = 0; kcp < 4; kcp++) {
                chunk(t * NKC + kcp, kcp);
                if (pending) {
#pragma unroll
                    for (int mt = 0; mt < 2; mt++)
#pragma unroll
                        for (int j = 0; j < 2; j++) {
                            const int nt = 2 * kcp + j;  // static
#pragma unroll
                            for (int d = 0; d < 4; d++)
                                rsum[mt][d >> 1] += ex2f(eacc[mt][nt][d]);
                        }
                }
            }
#pragma unroll 1
            for (int kc = 4; kc < NKC; kc++) chunk(t * NKC + kc, kc);

#pragma unroll
            for (int mt = 0; mt < 2; mt++)
#pragma unroll
                for (int nt = 0; nt < 8; nt++)
#pragma unroll
                    for (int d = 0; d < 4; d++) {
                        eacc[mt][nt][d] = acc[mt][nt][d];
                        acc[mt][nt][d] = 0.f;
                    }
            pending = true;
        }

#pragma unroll
        for (int mt = 0; mt < 2; mt++)
#pragma unroll
            for (int nt = 0; nt < 8; nt++)
#pragma unroll
                for (int d = 0; d < 4; d++)
                    rsum[mt][d >> 1] += ex2f(eacc[mt][nt][d]);

        // ---- per-job reduce: quad shuffle, then across the 2 N-warps ----
#pragma unroll
        for (int mt = 0; mt < 2; mt++)
#pragma unroll
            for (int h = 0; h < 2; h++) {
                float v = rsum[mt][h];
                v += __shfl_xor_sync(0xFFFFFFFFu, v, 1);
                v += __shfl_xor_sync(0xFFFFFFFFu, v, 2);
                rsum[mt][h] = v;
            }

        float* sred = (float*)sB;    // B buffers are free after last chunk
        __syncthreads();             // all warps done with compute/B reads
        if ((lane & 3) == 0) {
#pragma unroll
            for (int mt = 0; mt < 2; mt++)
#pragma unroll
                for (int h = 0; h < 2; h++) {
                    int rl = warp_m * 32 + mt * 16 + h * 8 + (lane >> 2);
                    sred[rl * 2 + warp_n] = rsum[mt][h];
                }
        }
        __syncthreads();
        if (tid < BM) g_rows[by][bx * BM + tid] = sred[tid * 2] + sred[tid * 2 + 1];
        __syncthreads();  // sred reads done before next job's loadB overwrites sB
    }
}

// ===================== kernel 3: loss reduction (1024 threads) =====================
__global__ void __launch_bounds__(1024) loss_kernel(float* __restrict__ out) {
    int tid = threadIdx.x;
    float acc = 0.f;
#pragma unroll 1
    for (int i = tid; i < Nn; i += 1024) {
        float r = 0.f;
#pragma unroll
        for (int s = 0; s < COLSPLIT; s++) r += g_rows[s][i];
        acc += logf(r) - g_diag[i] * LN2;   // diag is base-2 scaled (exact fp32)
    }
#pragma unroll
    for (int o = 16; o; o >>= 1) acc += __shfl_xor_sync(0xFFFFFFFFu, acc, o);
    __shared__ float sred[32];
    if ((tid & 31) == 0) sred[tid >> 5] = acc;
    __syncthreads();
    if (tid < 32) {
        float v = sred[tid];
#pragma unroll
        for (int o = 16; o; o >>= 1) v += __shfl_xor_sync(0xFFFFFFFFu, v, o);
        if (tid == 0) out[0] = v * (1.0f / (float)Nn);
    }
}

// ===================== launch =====================
extern "C" void kernel_launch(void* const* d_in, const int* in_sizes, int n_in,
                              void* d_out, int out_size) {
    const float* q = (const float*)d_in[0];
    const float* c = (const float*)d_in[1];
    float* out = (float*)d_out;

    cudaFuncSetAttribute(simcse_fused, cudaFuncAttributeMaxDynamicSharedMemorySize,
                         SMEM_BYTES);

    int nsm = 148;
    cudaDeviceGetAttribute(&nsm, cudaDevAttrMultiProcessorCount, 0);
    if (nsm < 1) nsm = 148;

    init_kernel<<<1, 128>>>();
    simcse_fused<<<nsm, 256, SMEM_BYTES>>>(q, c);
    loss_kernel<<<1, 1024>>>(out);
}